// round 1
// baseline (speedup 1.0000x reference)
#include <cuda_runtime.h>
#include <cuda_bf16.h>

#define FULL_MASK 0xffffffffu
#define EPW 128          // edges per warp
#define D   32           // feature dim (fixed by problem shape)

// counts scratch (no cudaMalloc allowed) — 4 MB, covers up to 1M segments
__device__ float g_counts[1 << 20];

// ---------------------------------------------------------------------------
// Kernel 1: zero output + counts
// ---------------------------------------------------------------------------
__global__ void k_zero(float* __restrict__ out, int out_n, int nseg) {
    int i = blockIdx.x * blockDim.x + threadIdx.x;
    if (i < out_n) out[i] = 0.0f;
    if (i < nseg)  g_counts[i] = 0.0f;
}

// ---------------------------------------------------------------------------
// Kernel 2: gather + sorted-segment sum (+ counts)
// lane = feature column; one warp processes EPW consecutive edges.
// Per 32-edge group: phase 1 issues all 32 row loads (MLP=32), phase 2 does
// the sequential run-length accumulate with rare atomic flushes on segment
// boundaries.
// ---------------------------------------------------------------------------
__global__ void __launch_bounds__(256)
k_agg(const float* __restrict__ src,
      const int*   __restrict__ gidx,
      const int*   __restrict__ sid,
      float*       __restrict__ out,
      int E)
{
    const int lane = threadIdx.x & 31;
    const long long warp  = ((long long)blockIdx.x * blockDim.x + threadIdx.x) >> 5;
    const long long start = warp * (long long)EPW;
    if (start >= E) return;
    const long long end = min(start + (long long)EPW, (long long)E);

    int   cur = -1;     // current segment (sentinel: ids are >= 0)
    float sum = 0.0f;
    int   cnt = 0;

    for (long long base = start; base < end; base += 32) {
        const int n = (int)min(32LL, end - base);

        int my_seg = 0, my_idx = 0;
        if (lane < n) {
            my_seg = __ldg(sid  + base + lane);   // coalesced
            my_idx = __ldg(gidx + base + lane);   // coalesced
        }

        if (n == 32) {
            // phase 1: independent gather loads -> MLP = 32
            float val[32];
            #pragma unroll
            for (int j = 0; j < 32; ++j) {
                int idx = __shfl_sync(FULL_MASK, my_idx, j);
                val[j] = __ldg(src + (long long)idx * D + lane);
            }
            // phase 2: run-length accumulate, flush on segment change
            #pragma unroll
            for (int j = 0; j < 32; ++j) {
                int seg = __shfl_sync(FULL_MASK, my_seg, j);
                if (seg != cur) {
                    if (cnt) {
                        atomicAdd(&out[(long long)cur * D + lane], sum);
                        if (lane == 0) atomicAdd(&g_counts[cur], (float)cnt);
                    }
                    cur = seg; sum = 0.0f; cnt = 0;
                }
                sum += val[j];
                ++cnt;
            }
        } else {
            // tail group (only the last group of the last warp)
            for (int j = 0; j < n; ++j) {
                int idx = __shfl_sync(FULL_MASK, my_idx, j);
                int seg = __shfl_sync(FULL_MASK, my_seg, j);
                float v = __ldg(src + (long long)idx * D + lane);
                if (seg != cur) {
                    if (cnt) {
                        atomicAdd(&out[(long long)cur * D + lane], sum);
                        if (lane == 0) atomicAdd(&g_counts[cur], (float)cnt);
                    }
                    cur = seg; sum = 0.0f; cnt = 0;
                }
                sum += v;
                ++cnt;
            }
        }
    }

    // final flush for this warp's chunk (boundary segments shared across
    // warps are handled correctly by the atomics)
    if (cnt) {
        atomicAdd(&out[(long long)cur * D + lane], sum);
        if (lane == 0) atomicAdd(&g_counts[cur], (float)cnt);
    }
}

// ---------------------------------------------------------------------------
// Kernel 3: out[n][d] /= max(count[n], 1)   (float4 vectorized, D=32 -> 8
// quads per row so each quad maps to exactly one segment)
// ---------------------------------------------------------------------------
__global__ void k_fin(float* __restrict__ out, int out_n) {
    int i = blockIdx.x * blockDim.x + threadIdx.x;
    int e = i * 4;
    if (e >= out_n) return;
    float4 v = reinterpret_cast<float4*>(out)[i];
    float  c = g_counts[e >> 5];           // e / D
    float  inv = 1.0f / fmaxf(c, 1.0f);
    v.x *= inv; v.y *= inv; v.z *= inv; v.w *= inv;
    reinterpret_cast<float4*>(out)[i] = v;
}

// ---------------------------------------------------------------------------
extern "C" void kernel_launch(void* const* d_in, const int* in_sizes, int n_in,
                              void* d_out, int out_size)
{
    const float* src  = (const float*)d_in[0];   // [N, 32] f32
    const int*   gidx = (const int*)  d_in[1];   // [E] i32
    const int*   sid  = (const int*)  d_in[2];   // [E] i32 (sorted)
    float*       out  = (float*)d_out;           // [N, 32] f32

    const int E    = in_sizes[1];
    const int nseg = out_size / D;               // N

    // 1) zero init (covers both out and counts)
    {
        int total   = out_size > nseg ? out_size : nseg;
        int threads = 256;
        int blocks  = (total + threads - 1) / threads;
        k_zero<<<blocks, threads>>>(out, out_size, nseg);
    }

    // 2) gather + segment sum
    {
        long long warps  = ((long long)E + EPW - 1) / EPW;
        long long tcount = warps * 32;
        int threads = 256;
        int blocks  = (int)((tcount + threads - 1) / threads);
        k_agg<<<blocks, threads>>>(src, gidx, sid, out, E);
    }

    // 3) divide by counts
    {
        int quads   = out_size / 4;
        int threads = 256;
        int blocks  = (quads + threads - 1) / threads;
        k_fin<<<blocks, threads>>>(out, out_size);
    }
}

// round 2
// speedup vs baseline: 1.7768x; 1.7768x over previous
#include <cuda_runtime.h>
#include <cuda_bf16.h>

#define FULL_MASK 0xffffffffu
#define EPW 128          // edges per warp-chunk (4 groups x 32 edges)
#define D   32           // feature dim (fixed by problem shape)

// counts scratch (no cudaMalloc allowed) — 4 MB, covers up to 1M segments
__device__ float g_counts[1 << 20];

// ---------------------------------------------------------------------------
// Kernel 1: zero output + counts (float4 vectorized)
// ---------------------------------------------------------------------------
__global__ void k_zero(float4* __restrict__ out4, int nq_out, int nq_cnt) {
    int i = blockIdx.x * blockDim.x + threadIdx.x;
    float4 z = make_float4(0.f, 0.f, 0.f, 0.f);
    if (i < nq_out) out4[i] = z;
    if (i < nq_cnt) reinterpret_cast<float4*>(g_counts)[i] = z;
}

// ---------------------------------------------------------------------------
// Flush helper: add partial segment sum into out + counts
// ---------------------------------------------------------------------------
__device__ __forceinline__ void flush_seg(float* __restrict__ out, int seg,
                                          float4 s, int cnt, int sub) {
    float* p = out + (long long)seg * D + sub * 4;
    atomicAdd(p + 0, s.x);
    atomicAdd(p + 1, s.y);
    atomicAdd(p + 2, s.z);
    atomicAdd(p + 3, s.w);
    if (sub == 0) atomicAdd(&g_counts[seg], (float)cnt);
}

// ---------------------------------------------------------------------------
// Kernel 2: gather + sorted-segment sum (+ counts)
// Warp = 4 groups of 8 lanes. Group g owns contiguous edges
// [start + g*32, start + g*32 + 32). Lane 'sub' (0..7) owns feature
// columns [sub*4, sub*4+4) as a float4. Per 8-edge batch: phase 1 issues 8
// independent LDG.128 row reads (MLP=8/lane), phase 2 does run-length
// accumulation with rare atomic flushes on segment change.
// ---------------------------------------------------------------------------
__global__ void __launch_bounds__(256)
k_agg(const float* __restrict__ src,
      const int*   __restrict__ gidx,
      const int*   __restrict__ sid,
      float*       __restrict__ out,
      int E)
{
    const int lane = threadIdx.x & 31;
    const int sub  = lane & 7;                    // position within group
    const long long warp  = ((long long)blockIdx.x * blockDim.x + threadIdx.x) >> 5;
    const long long start = warp * (long long)EPW;
    if (start >= E) return;

    if (start + EPW <= E) {
        // ---------- fast path: full 128-edge chunk ----------
        // each lane loads 4 consecutive ids -> warp covers 128 ids coalesced.
        // group g's edge j (0..31) lives in lane g*8 + (j>>2), component j&3,
        // reachable with width-8 shuffles.
        int4 gi4 = __ldg((const int4*)(gidx + start) + lane);
        int4 si4 = __ldg((const int4*)(sid  + start) + lane);
        int gi[4] = {gi4.x, gi4.y, gi4.z, gi4.w};
        int si[4] = {si4.x, si4.y, si4.z, si4.w};

        int    cur = -1;
        float4 sum = make_float4(0.f, 0.f, 0.f, 0.f);
        int    cnt = 0;

        #pragma unroll
        for (int jo = 0; jo < 32; jo += 8) {
            float4 val[8];
            #pragma unroll
            for (int jj = 0; jj < 8; ++jj) {
                const int j = jo + jj;
                int idx = __shfl_sync(FULL_MASK, gi[j & 3], j >> 2, 8);
                val[jj] = __ldg((const float4*)(src + (long long)idx * D) + sub);
            }
            #pragma unroll
            for (int jj = 0; jj < 8; ++jj) {
                const int j = jo + jj;
                int seg = __shfl_sync(FULL_MASK, si[j & 3], j >> 2, 8);
                if (seg != cur) {
                    if (cnt) flush_seg(out, cur, sum, cnt, sub);
                    cur = seg; sum = make_float4(0.f, 0.f, 0.f, 0.f); cnt = 0;
                }
                sum.x += val[jj].x; sum.y += val[jj].y;
                sum.z += val[jj].z; sum.w += val[jj].w;
                ++cnt;
            }
        }
        if (cnt) flush_seg(out, cur, sum, cnt, sub);
    } else {
        // ---------- tail path: partial chunk, per-group scalar loop ----------
        const int group = lane >> 3;
        long long gstart = start + (long long)group * 32;
        long long gend   = min(gstart + 32, (long long)E);

        int    cur = -1;
        float4 sum = make_float4(0.f, 0.f, 0.f, 0.f);
        int    cnt = 0;

        for (long long e = gstart; e < gend; ++e) {
            int idx = __ldg(gidx + e);
            int seg = __ldg(sid  + e);
            float4 v = __ldg((const float4*)(src + (long long)idx * D) + sub);
            if (seg != cur) {
                if (cnt) flush_seg(out, cur, sum, cnt, sub);
                cur = seg; sum = make_float4(0.f, 0.f, 0.f, 0.f); cnt = 0;
            }
            sum.x += v.x; sum.y += v.y; sum.z += v.z; sum.w += v.w;
            ++cnt;
        }
        if (cnt) flush_seg(out, cur, sum, cnt, sub);
    }
}

// ---------------------------------------------------------------------------
// Kernel 3: out[n][d] /= max(count[n], 1)   (float4; D=32 -> 8 quads/row)
// ---------------------------------------------------------------------------
__global__ void k_fin(float4* __restrict__ out4, int nq) {
    int i = blockIdx.x * blockDim.x + threadIdx.x;
    if (i >= nq) return;
    float4 v = out4[i];
    float  c = g_counts[i >> 3];          // (i*4) / 32
    float  inv = 1.0f / fmaxf(c, 1.0f);
    v.x *= inv; v.y *= inv; v.z *= inv; v.w *= inv;
    out4[i] = v;
}

// ---------------------------------------------------------------------------
extern "C" void kernel_launch(void* const* d_in, const int* in_sizes, int n_in,
                              void* d_out, int out_size)
{
    const float* src  = (const float*)d_in[0];   // [N, 32] f32
    const int*   gidx = (const int*)  d_in[1];   // [E] i32
    const int*   sid  = (const int*)  d_in[2];   // [E] i32 (sorted)
    float*       out  = (float*)d_out;           // [N, 32] f32

    const int E    = in_sizes[1];
    const int nseg = out_size / D;               // N

    // 1) zero init (out + counts), float4 stores
    {
        int nq_out = out_size / 4;
        int nq_cnt = (nseg + 3) / 4;
        int total  = nq_out > nq_cnt ? nq_out : nq_cnt;
        int threads = 256;
        int blocks  = (total + threads - 1) / threads;
        k_zero<<<blocks, threads>>>((float4*)out, nq_out, nq_cnt);
    }

    // 2) gather + segment sum
    {
        long long warps  = ((long long)E + EPW - 1) / EPW;
        long long tcount = warps * 32;
        int threads = 256;
        int blocks  = (int)((tcount + threads - 1) / threads);
        k_agg<<<blocks, threads>>>(src, gidx, sid, out, E);
    }

    // 3) divide by counts
    {
        int nq      = out_size / 4;
        int threads = 256;
        int blocks  = (nq + threads - 1) / threads;
        k_fin<<<blocks, threads>>>((float4*)out, nq);
    }
}

// round 3
// speedup vs baseline: 2.1006x; 1.1822x over previous
#include <cuda_runtime.h>
#include <cuda_bf16.h>

#define FULL_MASK 0xffffffffu
#define EPW 128          // edges per warp-chunk (4 groups x 32 edges)
#define D   32           // feature dim (fixed by problem shape)

// Scratch (no cudaMalloc allowed). Device globals are zero-initialized at
// module load; k_fin restores them to zero after each use, so every call of
// kernel_launch (correctness run + every graph replay) sees the same state.
__device__ float4 g_sums4[1 << 20];   // 16 MB: sums for up to 131072*... (N*8 quads; N<=131072)
__device__ float  g_counts[1 << 20];  // 4 MB: per-segment edge counts

// ---------------------------------------------------------------------------
// 128-bit reduction (fire-and-forget) — sm_90+ vector atomic
// ---------------------------------------------------------------------------
__device__ __forceinline__ void red_add_v4(float4* p, float4 s) {
    asm volatile("red.global.add.v4.f32 [%0], {%1, %2, %3, %4};"
                 :: "l"(p), "f"(s.x), "f"(s.y), "f"(s.z), "f"(s.w)
                 : "memory");
}

__device__ __forceinline__ void flush_seg(int seg, float4 s, int cnt, int sub) {
    red_add_v4(&g_sums4[seg * 8 + sub], s);
    if (sub == 0) atomicAdd(&g_counts[seg], (float)cnt);
}

// ---------------------------------------------------------------------------
// Kernel 1: gather + sorted-segment sum into scratch
// Warp = 4 groups of 8 lanes. Group g owns contiguous edges
// [start + g*32, start + g*32 + 32). Lane 'sub' (0..7) owns feature columns
// [sub*4, sub*4+4) as a float4. Phase 1 issues 8 independent LDG.128 row
// reads (MLP=8/lane); phase 2 run-length accumulates, flushing with one
// REDG.128 per lane on segment change.
// ---------------------------------------------------------------------------
__global__ void __launch_bounds__(256)
k_agg(const float* __restrict__ src,
      const int*   __restrict__ gidx,
      const int*   __restrict__ sid,
      int E)
{
    const int lane = threadIdx.x & 31;
    const int sub  = lane & 7;                    // position within group
    const long long warp  = ((long long)blockIdx.x * blockDim.x + threadIdx.x) >> 5;
    const long long start = warp * (long long)EPW;
    if (start >= E) return;

    if (start + EPW <= E) {
        // ---------- fast path: full 128-edge chunk ----------
        int4 gi4 = __ldg((const int4*)(gidx + start) + lane);
        int4 si4 = __ldg((const int4*)(sid  + start) + lane);
        int gi[4] = {gi4.x, gi4.y, gi4.z, gi4.w};
        int si[4] = {si4.x, si4.y, si4.z, si4.w};

        int    cur = -1;
        float4 sum = make_float4(0.f, 0.f, 0.f, 0.f);
        int    cnt = 0;

        #pragma unroll
        for (int jo = 0; jo < 32; jo += 8) {
            float4 val[8];
            #pragma unroll
            for (int jj = 0; jj < 8; ++jj) {
                const int j = jo + jj;
                int idx = __shfl_sync(FULL_MASK, gi[j & 3], j >> 2, 8);
                val[jj] = __ldg((const float4*)(src + (long long)idx * D) + sub);
            }
            #pragma unroll
            for (int jj = 0; jj < 8; ++jj) {
                const int j = jo + jj;
                int seg = __shfl_sync(FULL_MASK, si[j & 3], j >> 2, 8);
                if (seg != cur) {
                    if (cnt) flush_seg(cur, sum, cnt, sub);
                    cur = seg; sum = make_float4(0.f, 0.f, 0.f, 0.f); cnt = 0;
                }
                sum.x += val[jj].x; sum.y += val[jj].y;
                sum.z += val[jj].z; sum.w += val[jj].w;
                ++cnt;
            }
        }
        if (cnt) flush_seg(cur, sum, cnt, sub);
    } else {
        // ---------- tail path: partial chunk, per-group scalar loop ----------
        const int group = lane >> 3;
        long long gstart = start + (long long)group * 32;
        long long gend   = min(gstart + 32, (long long)E);

        int    cur = -1;
        float4 sum = make_float4(0.f, 0.f, 0.f, 0.f);
        int    cnt = 0;

        for (long long e = gstart; e < gend; ++e) {
            int idx = __ldg(gidx + e);
            int seg = __ldg(sid  + e);
            float4 v = __ldg((const float4*)(src + (long long)idx * D) + sub);
            if (seg != cur) {
                if (cnt) flush_seg(cur, sum, cnt, sub);
                cur = seg; sum = make_float4(0.f, 0.f, 0.f, 0.f); cnt = 0;
            }
            sum.x += v.x; sum.y += v.y; sum.z += v.z; sum.w += v.w;
            ++cnt;
        }
        if (cnt) flush_seg(cur, sum, cnt, sub);
    }
}

// ---------------------------------------------------------------------------
// Kernel 2: out[n][d] = sum/max(cnt,1), then restore scratch to zero.
// Thread i owns quad i (row = i>>3). Empty segments -> count 0 -> out 0,
// matching reference (0 / max(0,1)).
// ---------------------------------------------------------------------------
__global__ void k_fin(float4* __restrict__ out4, int nq) {
    int i = blockIdx.x * blockDim.x + threadIdx.x;
    if (i >= nq) return;
    float4 s = g_sums4[i];
    float  c = g_counts[i >> 3];
    float  inv = 1.0f / fmaxf(c, 1.0f);
    s.x *= inv; s.y *= inv; s.z *= inv; s.w *= inv;
    out4[i] = s;
    // restore the invariant for the next call / graph replay
    g_sums4[i] = make_float4(0.f, 0.f, 0.f, 0.f);
    if ((i & 7) == 0) g_counts[i >> 3] = 0.0f;
}

// ---------------------------------------------------------------------------
extern "C" void kernel_launch(void* const* d_in, const int* in_sizes, int n_in,
                              void* d_out, int out_size)
{
    const float* src  = (const float*)d_in[0];   // [N, 32] f32
    const int*   gidx = (const int*)  d_in[1];   // [E] i32
    const int*   sid  = (const int*)  d_in[2];   // [E] i32 (sorted)
    float*       out  = (float*)d_out;           // [N, 32] f32

    const int E = in_sizes[1];

    // 1) gather + segment sum into zeroed scratch
    {
        long long warps  = ((long long)E + EPW - 1) / EPW;
        long long tcount = warps * 32;
        int threads = 256;
        int blocks  = (int)((tcount + threads - 1) / threads);
        k_agg<<<blocks, threads>>>(src, gidx, sid, E);
    }

    // 2) mean + write out + re-zero scratch
    {
        int nq      = out_size / 4;
        int threads = 256;
        int blocks  = (nq + threads - 1) / threads;
        k_fin<<<blocks, threads>>>((float4*)out, nq);
    }
}